// round 12
// baseline (speedup 1.0000x reference)
#include <cuda_runtime.h>
#include <cstdint>

// Problem constants (fixed by setup_inputs)
#define NB 8
#define NH 100
#define NT 1000
#define NTS 80000   // NT * 80
#define BLK 256
#define NH2 (NH / 2)   // 50 harmonic pairs
#define NW 5           // interp columns per 256-sample window

// ---- shared mod-pi reduction constants (k < 2^19) ----
// pi = 3.125 + 17*2^-10 + c3; k*B1, k*B2 are EXACT fp32 products and the
// subtractions are Sterbenz-exact => reduction correct fused OR split.
#define INVPI  0.31830988618379067f
#define MAGIC  12582912.0f                  // 1.5 * 2^23
#define B1N    (-3.125f)
#define B2N    (-0.0166015625f)
#define C3P    (8.9089102e-6f)

// Taylor sin coefficients (odd, degree 7): err <= ~1.6e-4 on |r| <= pi/2
// (only 30% of harmonics use poly; contributes ~1e-5 rel, gate is 1e-3)
#define A3C (-1.6666667e-1f)
#define A5C ( 8.3333333e-3f)
#define A7C (-1.9841270e-4f)

typedef unsigned long long u64;

// ---- packed f32x2 helpers (Blackwell sm_103a) ----
__device__ __forceinline__ u64 pk2(float lo, float hi) {
    u64 r; asm("mov.b64 %0, {%1, %2};" : "=l"(r) : "f"(lo), "f"(hi)); return r;
}
__device__ __forceinline__ void upk2(float& lo, float& hi, u64 v) {
    asm("mov.b64 {%0, %1}, %2;" : "=f"(lo), "=f"(hi) : "l"(v));
}
__device__ __forceinline__ u64 mul2(u64 a, u64 b) {
    u64 r; asm("mul.rn.f32x2 %0, %1, %2;" : "=l"(r) : "l"(a), "l"(b)); return r;
}
__device__ __forceinline__ u64 add2(u64 a, u64 b) {
    u64 r; asm("add.rn.f32x2 %0, %1, %2;" : "=l"(r) : "l"(a), "l"(b)); return r;
}
__device__ __forceinline__ u64 fma2(u64 a, u64 b, u64 c) {
    u64 r; asm("fma.rn.f32x2 %0, %1, %2, %3;" : "=l"(r) : "l"(a), "l"(b), "l"(c)); return r;
}

// smem entry: one LDS.128 = two aligned u64 lane-pairs
struct __align__(16) QPair { u64 x0; u64 d; };   // (x0_h, x0_h+1), (d_h, d_h+1)

// poly pair at positions 2, 5, 8 of every 10 (f = 0.7 MUFU share, interleaved)
#define IS_POLY(h2) (((h2) % 10) == 2 || ((h2) % 10) == 5 || ((h2) % 10) == 8)

__global__ __launch_bounds__(BLK, 5)   // reg cap 51
void HarmonicOscillator_kernel(
    const float* __restrict__ f0,   // [B,1,T]
    const float* __restrict__ hd,   // [B,H,T]
    const float* __restrict__ ps,   // [B,1,T]
    float* __restrict__ out)        // [B,Ts]
{
    __shared__ QPair q[NH2 * NW];

    const int s0 = blockIdx.x * BLK;
    const int b  = blockIdx.y;
    const int s  = s0 + threadIdx.x;

    const float R = (float)(999.0 / 79999.0);   // (T-1)/(Ts-1) rounded like jax f32

    // Block-uniform window start (i0 monotone; spans <=5 values over 256 samples)
    int j0 = (int)__fmul_rn((float)s0, R);
    if (j0 > NT - 2) j0 = NT - 2;

    // --- cooperative smem fill: 250 pair-entries ---
    {
        const float* hb = hd + (size_t)b * (NH * NT);
        for (int idx = threadIdx.x; idx < NH2 * NW; idx += BLK) {
            int h2 = idx / NW;
            int j  = idx - h2 * NW;
            int g0 = j0 + j;  if (g0 > NT - 1) g0 = NT - 1;
            int g1 = g0 + 1;  if (g1 > NT - 1) g1 = NT - 1;
            const float* r0 = hb + (2 * h2) * NT;
            const float* r1 = r0 + NT;
            float a0 = __ldg(r0 + g0), a1 = __ldg(r0 + g1);
            float b0 = __ldg(r1 + g0), b1 = __ldg(r1 + g1);
            q[idx].x0 = pk2(a0, b0);
            q[idx].d  = pk2(__fsub_rn(a1, a0), __fsub_rn(b1, b0));
        }
    }
    __syncthreads();

    if (s >= NTS) return;

    // --- per-thread interpolation coords (match jnp f32 rounding exactly) ---
    float sF  = (float)s;
    float pos = __fmul_rn(sF, R);
    int i0 = (int)pos;                   // pos >= 0 -> trunc == floor
    if (i0 > NT - 2) i0 = NT - 2;
    float w = __fsub_rn(pos, (float)i0);
    int li = i0 - j0;                    // 0..4

    // --- f0 / phase_shift interp: x0 + (x1-x0)*w, separate roundings ---
    const float* f0b = f0 + b * NT;
    const float* psb = ps + b * NT;
    float fa = __ldg(f0b + i0), fb = __ldg(f0b + i0 + 1);
    float f0u = __fadd_rn(fa, __fmul_rn(__fsub_rn(fb, fa), w));
    float pa = __ldg(psb + i0), pb = __ldg(psb + i0 + 1);
    float psu = __fadd_rn(pa, __fmul_rn(__fsub_rn(pb, pa), w));

    // base = fl(fl(C * f0u) * t), C = fl(2*pi/16000)
    const float C = (float)(2.0 * 3.14159265358979323846 / 16000.0);
    float base = __fmul_rn(__fmul_rn(C, f0u), sF);

    const QPair* qp = q + li;

    // packed loop-invariant operands (single unified set)
    u64 psu2 = pk2(psu, psu);
    u64 w2   = pk2(w, w);
    u64 MG2  = pk2(MAGIC, MAGIC);
    u64 NMG2 = pk2(-MAGIC, -MAGIC);
    u64 INV2 = pk2(INVPI, INVPI);
    u64 B1_2 = pk2(B1N, B1N);
    u64 B2_2 = pk2(B2N, B2N);
    u64 C3_2 = pk2(C3P, C3P);
    u64 A7_2 = pk2(A7C, A7C);
    u64 A5_2 = pk2(A5C, A5C);
    u64 A3_2 = pk2(A3C, A3C);

    u64 accM = pk2(0.0f, 0.0f);   // MUFU-path accumulator
    u64 accP = pk2(0.0f, 0.0f);   // poly-path accumulator

    #pragma unroll
    for (int h2 = 0; h2 < NH2; ++h2) {
        QPair v = qp[h2 * NW];                       // one LDS.128

        // X = fl(fl(base*h) + psu) per lane -- bit-exact vs reference
        float p0 = __fmul_rn(base, (float)(2 * h2 + 1));  // FMUL-imm
        float p1 = __fmul_rn(base, (float)(2 * h2 + 2));
        u64 X2 = add2(pk2(p0, p1), psu2);

        // shared fusion-independent reduction mod pi: r in [-pi/2-eps, pi/2+eps]
        u64 kb2 = fma2(X2, INV2, MG2);     // k = round(X/pi) in mantissa
        u64 kf2 = add2(kb2, NMG2);         // exact k as float
        u64 r2  = fma2(kf2, B1_2, X2);     // exact
        r2      = fma2(kf2, B2_2, r2);     // exact
        r2      = fma2(kf2, C3_2, r2);     // ~3e-7 fused or split

        // sign = (-1)^k folded into r (sin is odd) -- ALU pipe
        u64 sgn = (kb2 & 0x0000000100000001ULL) << 31;
        r2 ^= sgn;

        if (!IS_POLY(h2)) {
            // ===== MUFU pair (7 of 10): XU-pipe sine =====
            float r0, r1; upk2(r0, r1, r2);
            u64 s2 = pk2(__sinf(r0), __sinf(r1));    // 2x MUFU.SIN
            accM = fma2(s2, fma2(v.d, w2, v.x0), accM);
        } else {
            // ===== poly pair (3 of 10): fma-pipe Taylor-7 sine =====
            u64 q2 = mul2(r2, r2);
            u64 pp = fma2(A7_2, q2, A5_2);
            pp = fma2(pp, q2, A3_2);
            u64 rq = mul2(r2, q2);
            u64 s2 = fma2(pp, rq, r2);               // r + r*q*P(q)
            accP = fma2(s2, fma2(v.d, w2, v.x0), accP);
        }
    }

    u64 acc2 = add2(accM, accP);
    float a0, a1; upk2(a0, a1, acc2);
    out[(size_t)b * NTS + s] = __fadd_rn(a0, a1);
}

extern "C" void kernel_launch(void* const* d_in, const int* in_sizes, int n_in,
                              void* d_out, int out_size) {
    const float* f0 = (const float*)d_in[0];
    const float* hd = (const float*)d_in[1];
    const float* ps = (const float*)d_in[2];
    float* out = (float*)d_out;

    dim3 block(BLK);
    dim3 grid((NTS + BLK - 1) / BLK, NB);
    HarmonicOscillator_kernel<<<grid, block>>>(f0, hd, ps, out);
}

// round 13
// speedup vs baseline: 1.1262x; 1.1262x over previous
#include <cuda_runtime.h>
#include <cstdint>

// Problem constants (fixed by setup_inputs)
#define NB 8
#define NH 100
#define NT 1000
#define NTS 80000   // NT * 80
#define BLK 256
#define NH2 (NH / 2)   // 50 harmonic pairs
#define NW 5           // interp columns per 256-sample window

// mod-2pi constants
#define INV2PI 0.15915494309189535f
#define MAGIC  12582912.0f                 // 1.5 * 2^23
// fusion-independent 3-term split of 2*pi (k < 2^18):
//   HI1 = 6.25 (5-bit sig: k*HI1 exact), HI2 = 17*2^-9 (exact), C3 = HI1+HI2-2pi
#define NHI1 (-6.25f)
#define NHI2 (-0.033203125f)
#define C3   (1.7817820414e-5f)

typedef unsigned long long u64;

// ---- packed f32x2 helpers (Blackwell sm_103a) ----
__device__ __forceinline__ u64 pk2(float lo, float hi) {
    u64 r; asm("mov.b64 %0, {%1, %2};" : "=l"(r) : "f"(lo), "f"(hi)); return r;
}
__device__ __forceinline__ void upk2(float& lo, float& hi, u64 v) {
    asm("mov.b64 {%0, %1}, %2;" : "=f"(lo), "=f"(hi) : "l"(v));
}
__device__ __forceinline__ u64 add2(u64 a, u64 b) {
    u64 r; asm("add.rn.f32x2 %0, %1, %2;" : "=l"(r) : "l"(a), "l"(b)); return r;
}
__device__ __forceinline__ u64 fma2(u64 a, u64 b, u64 c) {
    u64 r; asm("fma.rn.f32x2 %0, %1, %2, %3;" : "=l"(r) : "l"(a), "l"(b), "l"(c)); return r;
}

// smem entry: one LDS.128 = two aligned u64 lane-pairs
struct __align__(16) QPair { u64 x0; u64 d; };   // (x0_h, x0_h+1), (d_h, d_h+1)

// packed 2-harmonic sin with fusion-independent mod-2pi reduction
__device__ __forceinline__ u64 sin2_exact(
    u64 X2, u64 INV2, u64 MG2, u64 NMG2, u64 NH1_2, u64 NH2_2, u64 C3_2)
{
    u64 kb2 = fma2(X2, INV2, MG2);
    u64 kf2 = add2(kb2, NMG2);
    u64 d1  = fma2(kf2, NH1_2, X2);   // exact (k*6.25 exact product)
    u64 d2  = fma2(kf2, NH2_2, d1);   // exact
    u64 r2  = fma2(kf2, C3_2, d2);    // ~2e-7 err fused or split
    float r0, r1; upk2(r0, r1, r2);
    return pk2(__sinf(r0), __sinf(r1));
}

__global__ __launch_bounds__(BLK, 6)   // reg cap 42: let ptxas overlap iterations
void HarmonicOscillator_kernel(
    const float* __restrict__ f0,   // [B,1,T]
    const float* __restrict__ hd,   // [B,H,T]
    const float* __restrict__ ps,   // [B,1,T]
    float* __restrict__ out)        // [B,Ts]
{
    __shared__ QPair q[NH2 * NW];

    const int s0 = blockIdx.x * BLK;
    const int b  = blockIdx.y;
    const int s  = s0 + threadIdx.x;

    const float R = (float)(999.0 / 79999.0);   // (T-1)/(Ts-1) rounded like jax f32

    // Block-uniform window start (i0 monotone; spans <=5 values over 256 samples)
    int j0 = (int)__fmul_rn((float)s0, R);
    if (j0 > NT - 2) j0 = NT - 2;

    // --- cooperative smem fill: 250 pair-entries ---
    {
        const float* hb = hd + (size_t)b * (NH * NT);
        for (int idx = threadIdx.x; idx < NH2 * NW; idx += BLK) {
            int h2 = idx / NW;
            int j  = idx - h2 * NW;
            int g0 = j0 + j;  if (g0 > NT - 1) g0 = NT - 1;
            int g1 = g0 + 1;  if (g1 > NT - 1) g1 = NT - 1;
            const float* r0 = hb + (2 * h2) * NT;
            const float* r1 = r0 + NT;
            float a0 = __ldg(r0 + g0), a1 = __ldg(r0 + g1);
            float b0 = __ldg(r1 + g0), b1 = __ldg(r1 + g1);
            q[idx].x0 = pk2(a0, b0);
            q[idx].d  = pk2(__fsub_rn(a1, a0), __fsub_rn(b1, b0));
        }
    }
    __syncthreads();

    if (s >= NTS) return;

    // --- per-thread interpolation coords (match jnp f32 rounding exactly) ---
    float sF  = (float)s;
    float pos = __fmul_rn(sF, R);
    int i0 = (int)pos;                   // pos >= 0 -> trunc == floor
    if (i0 > NT - 2) i0 = NT - 2;
    float w = __fsub_rn(pos, (float)i0);
    int li = i0 - j0;                    // 0..4

    // --- f0 / phase_shift interp: x0 + (x1-x0)*w, separate roundings ---
    const float* f0b = f0 + b * NT;
    const float* psb = ps + b * NT;
    float fa = __ldg(f0b + i0), fb = __ldg(f0b + i0 + 1);
    float f0u = __fadd_rn(fa, __fmul_rn(__fsub_rn(fb, fa), w));
    float pa = __ldg(psb + i0), pb = __ldg(psb + i0 + 1);
    float psu = __fadd_rn(pa, __fmul_rn(__fsub_rn(pb, pa), w));

    // base = fl(fl(C * f0u) * t), C = fl(2*pi/16000)
    const float C = (float)(2.0 * 3.14159265358979323846 / 16000.0);
    float base = __fmul_rn(__fmul_rn(C, f0u), sF);

    const QPair* qp = q + li;

    // packed loop-invariant operands
    u64 psu2  = pk2(psu, psu);
    u64 w2    = pk2(w, w);
    u64 INV2  = pk2(INV2PI, INV2PI);
    u64 MG2   = pk2(MAGIC, MAGIC);
    u64 NMG2  = pk2(-MAGIC, -MAGIC);
    u64 NH1_2 = pk2(NHI1, NHI1);
    u64 NH2_2 = pk2(NHI2, NHI2);
    u64 C3_2  = pk2(C3, C3);

    u64 acc2  = pk2(0.0f, 0.0f);

    #pragma unroll
    for (int h2 = 0; h2 < NH2; ++h2) {
        QPair v = qp[h2 * NW];                       // one LDS.128

        // X = fl(fl(base*h) + psu) per lane -- bit-exact vs reference
        float p0 = __fmul_rn(base, (float)(2 * h2 + 1));   // FMUL-imm
        float p1 = __fmul_rn(base, (float)(2 * h2 + 2));
        u64 X2 = add2(pk2(p0, p1), psu2);

        u64 s2 = sin2_exact(X2, INV2, MG2, NMG2, NH1_2, NH2_2, C3_2);

        // harmonic_dist interp + accumulate
        acc2 = fma2(s2, fma2(v.d, w2, v.x0), acc2);
    }

    float a0, a1; upk2(a0, a1, acc2);
    out[(size_t)b * NTS + s] = __fadd_rn(a0, a1);
}

extern "C" void kernel_launch(void* const* d_in, const int* in_sizes, int n_in,
                              void* d_out, int out_size) {
    const float* f0 = (const float*)d_in[0];
    const float* hd = (const float*)d_in[1];
    const float* ps = (const float*)d_in[2];
    float* out = (float*)d_out;

    dim3 block(BLK);
    dim3 grid((NTS + BLK - 1) / BLK, NB);
    HarmonicOscillator_kernel<<<grid, block>>>(f0, hd, ps, out);
}